// round 7
// baseline (speedup 1.0000x reference)
#include <cuda_runtime.h>
#include <math.h>

// F0Resonance: out[b,e,s] = normalize_s( sum_o w_o * sin(phase_o[s]) )
//
// Numerics model H4: JAX lowers cumsum to reduce_window on CPU+GPU; XLA's
// ReduceWindowRewriter (base_length = 16, the xla_reduce_window_rewrite_base_length
// default) recursively decomposes the 32768 scan: 32768 -> 2048 -> 128 -> 8.
// For constant addend c (0-based sample s, chunk g = s>>4, r = s&15):
//   LA[r] = seqfold_{r+1}(c), TA = LA[15]
//   LB[r] = seqfold_{r+1}(TA), TB = LB[15]
//   LC[r] = seqfold_{r+1}(TB), TC = LC[15]
//   SD[j] = seqfold_{j+1}(TC)                       (8 <= 16: naive)
//   SC[m] = fl(ED(m>>4) + LC[m&15]),  ED(i)=SD[i-1] (0 if i==0)
//   SB[m] = fl(EC(m>>4) + LB[m&15]),  EC(i)=SC[i-1] (0 if i==0)
//   phase(s) = fl(EB(g) + LA[r]),     EB(g)=SB[g-1] (0 if g==0)
// Octave-axis cumsums (N=16 <= base): naive sequential folds.
// theta path: separate mul/add roundings.

#define NSAMP  32768
#define NOCT   16
#define NEV    256           // B*E = 4*64
#define THREADS 512
#define SPT    64            // samples per thread: groups 4t..4t+3 of 16

// sin for args up to ~2^19: 3-term FMA Cody-Waite reduction mod 2*pi
// (err ~4e-7 rad), then MUFU __sinf (abs err ~2^-21.4). Total << 1e-3.
__device__ __forceinline__ float reduced_sin(float x) {
    const double TWO_PI_D = 6.283185307179586476925286766559;
    const float T1 = (float)TWO_PI_D;
    const float T2 = (float)(TWO_PI_D - (double)T1);
    const float T3 = (float)(TWO_PI_D - (double)T1 - (double)T2);
    const float INV_2PI = (float)(1.0 / TWO_PI_D);
    float kf = rintf(__fmul_rn(x, INV_2PI));
    float r = fmaf(kf, -T1, x);
    r = fmaf(kf, -T2, r);
    r = fmaf(kf, -T3, r);
    return __sinf(r);
}

__global__ void __launch_bounds__(THREADS, 1)
f0res_kernel(const float* __restrict__ f0_in,
             const float* __restrict__ dc_in,
             const float* __restrict__ fs_in,
             float* __restrict__ out) {
    const int ev = blockIdx.x;      // 0..255 = b*64 + e
    const int tid = threadIdx.x;

    __shared__ float sh_LA[NOCT][16];
    __shared__ float sh_LB[NOCT][16];
    __shared__ float sh_ECt[NOCT][128];   // EC(i): 0 if i==0 else SC[i-1]
    __shared__ float sh_w[NOCT];
    __shared__ float sh_wmax[THREADS / 32];
    __shared__ float sh_denom;

    // ---- Prolog: per-octave theta, weight, scan tables (threads 0..15) ----
    if (tid < NOCT) {
        const int o = tid;
        const int n = o + 1;
        const float MIN_FREQ_F   = (float)(20.0 / 11025.0);
        const float FREQ_RANGE_F = (float)(3000.0 / 11025.0 - 20.0 / 11025.0);
        const float PI_F = 3.14159265358979323846f;

        float f0 = fabsf(f0_in[ev]);
        // (MIN_FREQ + f0 * FREQ_RANGE) * pi  -- separate roundings
        float f0a = __fmul_rn(__fadd_rn(MIN_FREQ_F, __fmul_rn(f0, FREQ_RANGE_F)), PI_F);

        // factors[o]: naive reduce_window cumsum = sequential fold
        float fs = fs_in[ev];
        float fac = fs;
        for (int i = 1; i < n; i++) fac = __fadd_rn(fac, fs);
        const float th = __fmul_rn(f0a, fac);

        // weights: exp( seq-fold cumsum of log(0.01 + sig(sig(dc))*0.9405) )
        float dc = dc_in[ev];
        float s1 = 1.0f / (1.0f + expf(-dc));
        float s2 = 1.0f / (1.0f + expf(-s1));
        float decay = __fadd_rn(0.01f, __fmul_rn(s2, (float)((1.0 - 0.01) * 0.95)));
        float ld = logf(__fadd_rn(decay, 1e-12f));
        float cum = ld;
        for (int i = 1; i < n; i++) cum = __fadd_rn(cum, ld);
        sh_w[o] = expf(cum);

        // Level tables (base-16 recursive ReduceWindowRewriter trajectory)
        float LC[16], SD[8];
        float acc = 0.f;
        for (int r = 0; r < 16; r++) { acc = __fadd_rn(acc, th); sh_LA[o][r] = acc; }
        const float TA = acc;
        acc = 0.f;
        for (int r = 0; r < 16; r++) { acc = __fadd_rn(acc, TA); sh_LB[o][r] = acc; }
        const float TB = acc;
        acc = 0.f;
        for (int r = 0; r < 16; r++) { acc = __fadd_rn(acc, TB); LC[r] = acc; }
        const float TC = acc;
        acc = 0.f;
        for (int j = 0; j < 8; j++) { acc = __fadd_rn(acc, TC); SD[j] = acc; }

        // SC[m] = fl(ED(m>>4) + LC[m&15]);  ECt[i] = (i==0) ? 0 : SC[i-1]
        sh_ECt[o][0] = 0.f;
        for (int m = 0; m < 127; m++) {
            const int i3 = m >> 4, r3 = m & 15;
            float ED = (i3 == 0) ? 0.f : SD[i3 - 1];
            sh_ECt[o][m + 1] = __fadd_rn(ED, LC[r3]);
        }
    }
    __syncthreads();

    // ---- Main: thread t owns samples [64t, 64t+64) = groups 4t..4t+3 ----
    float osc[SPT];
#pragma unroll
    for (int k = 0; k < SPT; k++) osc[k] = 0.f;

#pragma unroll
    for (int gg = 0; gg < 4; gg++) {
        const int g = tid * 4 + gg;       // 16-sample group index (= i1)
        const int m = g - 1;
        const int mi = m >> 4, mr = m & 15;
#pragma unroll
        for (int o = 0; o < NOCT; o++) {
            // EB(g) = 0 if g==0 else fl(ECt[m>>4] + LB[m&15])
            float EB = (g == 0) ? 0.f
                                : __fadd_rn(sh_ECt[o][mi], sh_LB[o][mr]);
            const float w = sh_w[o];
#pragma unroll
            for (int r = 0; r < 16; r++) {
                float p = __fadd_rn(EB, sh_LA[o][r]);   // fl(EB + LA[r])
                float sv = reduced_sin(p);
                const int k = gg * 16 + r;
                osc[k] = __fadd_rn(osc[k], __fmul_rn(sv, w));
            }
        }
    }

    // ---- Block-wide max(|osc|) ----
    float mmax = 0.f;
#pragma unroll
    for (int k = 0; k < SPT; k++) mmax = fmaxf(mmax, fabsf(osc[k]));
#pragma unroll
    for (int off = 16; off; off >>= 1)
        mmax = fmaxf(mmax, __shfl_xor_sync(0xffffffffu, mmax, off));
    if ((tid & 31) == 0) sh_wmax[tid >> 5] = mmax;
    __syncthreads();
    if (tid == 0) {
        float mm = sh_wmax[0];
#pragma unroll
        for (int i = 1; i < THREADS / 32; i++) mm = fmaxf(mm, sh_wmax[i]);
        sh_denom = __fadd_rn(mm, 1e-8f);
    }
    __syncthreads();
    const float denom = sh_denom;

    // ---- Normalize + store (float4; thread strip is contiguous) ----
    float4* op = (float4*)(out + (size_t)ev * NSAMP + tid * SPT);
#pragma unroll
    for (int k = 0; k < SPT; k += 4) {
        float4 v;
        v.x = osc[k + 0] / denom;
        v.y = osc[k + 1] / denom;
        v.z = osc[k + 2] / denom;
        v.w = osc[k + 3] / denom;
        op[k >> 2] = v;
    }
}

extern "C" void kernel_launch(void* const* d_in, const int* in_sizes, int n_in,
                              void* d_out, int out_size) {
    const float* f0 = (const float*)d_in[0];
    const float* dc = (const float*)d_in[1];
    // d_in[2] = phase_offsets: computed but unused by the reference
    const float* fs = (const float*)d_in[3];
    f0res_kernel<<<NEV, THREADS>>>(f0, dc, fs, (float*)d_out);
}

// round 8
// speedup vs baseline: 3.0991x; 3.0991x over previous
#include <cuda_runtime.h>
#include <math.h>

// F0Resonance: out[b,e,s] = normalize_s( sum_o w_o * sin(phase_o[s]) )
//
// Numerics model H4 (VALIDATED R7, rel_err 2.3e-7): cumsum -> reduce_window;
// XLA ReduceWindowRewriter (base_length=16) recursive decomposition
// 32768 -> 2048 -> 128 -> 8. For 0-based sample s, g=s>>4, r=s&15:
//   phase(s) = fl(EB(g) + LA[r]);  EB(g) = 0 if g==0 else fl(ECt[(g-1)>>4] + LB[(g-1)&15])
// Octave-axis cumsums (N=16): naive sequential folds. theta: separate mul/add.
// DO NOT change any rounding below — it is bit-matched to the reference.

#define NSAMP  32768
#define NOCT   16
#define NEV    256            // B*E = 4*64
#define K1T    512            // 16 warps; each warp owns 256 samples
#define QY     8              // grid.y: 8 * 16 warps * 256 samples = 32768
#define K2T    512

__device__ float g_partmax[NEV * QY];

// sin for args up to ~2^19: 3-term FMA Cody-Waite reduction mod 2*pi
// (err ~4e-7 rad), then MUFU __sinf (abs err ~2^-21.4). Total << 1e-3.
__device__ __forceinline__ float reduced_sin(float x) {
    const double TWO_PI_D = 6.283185307179586476925286766559;
    const float T1 = (float)TWO_PI_D;
    const float T2 = (float)(TWO_PI_D - (double)T1);
    const float T3 = (float)(TWO_PI_D - (double)T1 - (double)T2);
    const float INV_2PI = (float)(1.0 / TWO_PI_D);
    float kf = rintf(__fmul_rn(x, INV_2PI));
    float r = fmaf(kf, -T1, x);
    r = fmaf(kf, -T2, r);
    r = fmaf(kf, -T3, r);
    return __sinf(r);
}

__global__ void __launch_bounds__(K1T, 4)
f0res_main(const float* __restrict__ f0_in,
           const float* __restrict__ dc_in,
           const float* __restrict__ fs_in,
           float* __restrict__ out) {
    const int ev   = blockIdx.x;          // 0..255
    const int q    = blockIdx.y;          // 0..7
    const int tid  = threadIdx.x;
    const int warp = tid >> 5;
    const int lane = tid & 31;

    __shared__ float sh_LA[NOCT][16];
    __shared__ float sh_LB[NOCT][16];
    __shared__ float sh_LC[NOCT][16];
    __shared__ float sh_SD[NOCT][8];
    __shared__ float sh_ECt[NOCT][128];   // EC(i): 0 if i==0 else SC[i-1]
    __shared__ float sh_w[NOCT];
    __shared__ float sh_wmax[K1T / 32];

    // ---- Prolog: per-octave theta, weight, scan tables (threads 0..15) ----
    if (tid < NOCT) {
        const int o = tid;
        const int n = o + 1;
        const float MIN_FREQ_F   = (float)(20.0 / 11025.0);
        const float FREQ_RANGE_F = (float)(3000.0 / 11025.0 - 20.0 / 11025.0);
        const float PI_F = 3.14159265358979323846f;

        float f0 = fabsf(f0_in[ev]);
        float f0a = __fmul_rn(__fadd_rn(MIN_FREQ_F, __fmul_rn(f0, FREQ_RANGE_F)), PI_F);

        float fs = fs_in[ev];
        float fac = fs;
        for (int i = 1; i < n; i++) fac = __fadd_rn(fac, fs);
        const float th = __fmul_rn(f0a, fac);

        float dc = dc_in[ev];
        float s1 = 1.0f / (1.0f + expf(-dc));
        float s2 = 1.0f / (1.0f + expf(-s1));
        float decay = __fadd_rn(0.01f, __fmul_rn(s2, (float)((1.0 - 0.01) * 0.95)));
        float ld = logf(__fadd_rn(decay, 1e-12f));
        float cum = ld;
        for (int i = 1; i < n; i++) cum = __fadd_rn(cum, ld);
        sh_w[o] = expf(cum);

        float acc = 0.f;
        for (int r = 0; r < 16; r++) { acc = __fadd_rn(acc, th); sh_LA[o][r] = acc; }
        const float TA = acc;
        acc = 0.f;
        for (int r = 0; r < 16; r++) { acc = __fadd_rn(acc, TA); sh_LB[o][r] = acc; }
        const float TB = acc;
        acc = 0.f;
        for (int r = 0; r < 16; r++) { acc = __fadd_rn(acc, TB); sh_LC[o][r] = acc; }
        const float TC = acc;
        acc = 0.f;
        for (int j = 0; j < 8; j++) { acc = __fadd_rn(acc, TC); sh_SD[o][j] = acc; }

        sh_ECt[o][0] = 0.f;
        for (int m = 0; m < 127; m++) {
            const int i3 = m >> 4, r3 = m & 15;
            float ED = (i3 == 0) ? 0.f : sh_SD[o][i3 - 1];
            sh_ECt[o][m + 1] = __fadd_rn(ED, sh_LC[o][r3]);
        }
    }
    __syncthreads();

    // ---- Main: warp W owns samples [W*256, W*256+256) ----
    // lane l handles s = W*256 + j*32 + l, j=0..7  =>  r = l & 15 fixed,
    // g = W*16 + j*2 + (l>>4). Stores are lane-coalesced.
    const int W    = q * 16 + warp;       // 0..127
    const int r    = lane & 15;
    const int half = lane >> 4;

    float acc[8];
#pragma unroll
    for (int j = 0; j < 8; j++) acc[j] = 0.f;

#pragma unroll
    for (int o = 0; o < NOCT; o++) {
        const float lav = sh_LA[o][r];     // conflict-free (16 banks x2 bcast)
        const float wv  = sh_w[o];         // broadcast
#pragma unroll
        for (int j = 0; j < 8; j++) {
            const int g  = W * 16 + j * 2 + half;
            const int m  = (g > 0) ? (g - 1) : 0;
            const int mi = m >> 4, mr = m & 15;
            float EB = __fadd_rn(sh_ECt[o][mi], sh_LB[o][mr]);
            if (g == 0) EB = 0.f;
            float p  = __fadd_rn(EB, lav);             // fl(EB + LA[r])
            float sv = reduced_sin(p);
            acc[j] = __fadd_rn(acc[j], __fmul_rn(sv, wv));
        }
    }

    // ---- Store raw osc (coalesced) + per-thread max ----
    float* op = out + (size_t)ev * NSAMP + W * 256;
    float mx = 0.f;
#pragma unroll
    for (int j = 0; j < 8; j++) {
        op[j * 32 + lane] = acc[j];
        mx = fmaxf(mx, fabsf(acc[j]));
    }

    // ---- Block max -> scratch ----
#pragma unroll
    for (int off = 16; off; off >>= 1)
        mx = fmaxf(mx, __shfl_xor_sync(0xffffffffu, mx, off));
    if (lane == 0) sh_wmax[warp] = mx;
    __syncthreads();
    if (tid == 0) {
        float mm = sh_wmax[0];
#pragma unroll
        for (int i = 1; i < K1T / 32; i++) mm = fmaxf(mm, sh_wmax[i]);
        g_partmax[ev * QY + q] = mm;
    }
}

__global__ void __launch_bounds__(K2T)
f0res_norm(float* __restrict__ out) {
    const int ev  = blockIdx.x;
    const int tid = threadIdx.x;
    __shared__ float sh_denom;
    if (tid == 0) {
        float mm = g_partmax[ev * QY];
#pragma unroll
        for (int i = 1; i < QY; i++) mm = fmaxf(mm, g_partmax[ev * QY + i]);
        sh_denom = __fadd_rn(mm, 1e-8f);
    }
    __syncthreads();
    const float denom = sh_denom;

    float4* p = (float4*)(out + (size_t)ev * NSAMP);
#pragma unroll
    for (int k = tid; k < NSAMP / 4; k += K2T) {
        float4 v = p[k];
        v.x = v.x / denom;
        v.y = v.y / denom;
        v.z = v.z / denom;
        v.w = v.w / denom;
        p[k] = v;
    }
}

extern "C" void kernel_launch(void* const* d_in, const int* in_sizes, int n_in,
                              void* d_out, int out_size) {
    const float* f0 = (const float*)d_in[0];
    const float* dc = (const float*)d_in[1];
    // d_in[2] = phase_offsets: computed but unused by the reference
    const float* fs = (const float*)d_in[3];
    f0res_main<<<dim3(NEV, QY), K1T>>>(f0, dc, fs, (float*)d_out);
    f0res_norm<<<NEV, K2T>>>((float*)d_out);
}